// round 2
// baseline (speedup 1.0000x reference)
#include <cuda_runtime.h>

// Flow1: K=32, B=4096, ZS=128, ZH=64, HS=50, NF=2
#define KK   32
#define BB   4096
#define ZSv  128
#define ZHv  64
#define HSv  50
#define HSP  52            // HS padded to multiple of 4 (zero-padded)
#define ROWS (KK*BB)       // 131072
#define TPB  128
#define RPC  128           // rows per CTA (thread-per-row)
#define NBLK (ROWS/RPC)    // 1024
#define ZSTR 65            // passive z half row stride (conflict-free scalar LDS)

#define SMEM_FLOATS (RPC*ZSTR + HSP*ZHv + 2*ZHv*HSP + HSP + 2*ZHv + RPC*4)
#define SMEM_BYTES  (SMEM_FLOATS * 4)   // ~74.2 KB -> 3 CTAs/SM

typedef unsigned long long ull;

__device__ __forceinline__ ull ffma2(ull a, ull b, ull c) {
    ull d;
    asm("fma.rn.f32x2 %0, %1, %2, %3;" : "=l"(d) : "l"(a), "l"(b), "l"(c));
    return d;
}
__device__ __forceinline__ ull pack2(float lo, float hi) {
    ull r;
    asm("mov.b64 %0, {%1, %2};" : "=l"(r) : "f"(lo), "f"(hi));
    return r;
}
__device__ __forceinline__ float2 unpack2(ull v) {
    float lo, hi;
    asm("mov.b64 {%0, %1}, %2;" : "=f"(lo), "=f"(hi) : "l"(v));
    return make_float2(lo, hi);
}
__device__ __forceinline__ float fast_tanh(float x) {
    float e = __expf(-2.f * fabsf(x));
    float t = __fdividef(1.f - e, 1.f + e);
    return copysignf(t, x);
}

__global__ void __launch_bounds__(TPB, 3) flow_kernel(
    const float* __restrict__ mean, const float* __restrict__ logvar,
    const float* __restrict__ eps,
    const float* __restrict__ W0, const float* __restrict__ b0,
    const float* __restrict__ W1, const float* __restrict__ b1,
    const float* __restrict__ W2, const float* __restrict__ b2,
    float* __restrict__ out)
{
    extern __shared__ float sm[];
    float* zsh     = sm;                    // [RPC][ZSTR] : passive z half
    float* w0sh    = zsh  + RPC*ZSTR;       // [HSP][ZHv]  rows j>=50 zero
    float* w1sh    = w0sh + HSP*ZHv;        // [ZHv][HSP]  cols j>=50 zero
    float* w2sh    = w1sh + ZHv*HSP;        // [ZHv][HSP]
    float* b0sh    = w2sh + ZHv*HSP;        // [HSP] (pad zero)
    float* b1sh    = b0sh + HSP;            // [ZHv]
    float* b2sh    = b1sh + ZHv;            // [ZHv]
    float* rowpart = b2sh + ZHv;            // [RPC][4]

    const int tid  = threadIdx.x;
    const int lane = tid & 31;
    const size_t r0    = (size_t)blockIdx.x * RPC;
    const size_t bbase = (size_t)(r0 & (BB-1)) * ZSv;

    ull zp[32];            // active (source) z half, packed pairs, register-resident

    // ---------------- prologue pass A: z1 (cols 0..63) -> smem stage -> regs ----
    #pragma unroll 4
    for (int it = 0; it < 64; it++) {
        int idx = it * TPB + tid;          // enumerates (row, col) over 128x64
        int row = idx >> 6, col = idx & 63;
        size_t go = (size_t)row * ZSv + col;
        float ep = eps[r0*ZSv + go];
        float lv = logvar[bbase + go];
        float mn = mean[bbase + go];
        zsh[row*ZSTR + col] = fmaf(ep, __expf(0.5f*lv), mn);
        float c = fmaf(ep, ep, lv);
        #pragma unroll
        for (int o = 16; o; o >>= 1) c += __shfl_xor_sync(0xFFFFFFFFu, c, o);
        if (lane == 0) rowpart[row*4 + ((tid >> 5) & 1)] = c;
    }
    __syncthreads();
    #pragma unroll
    for (int m = 0; m < 32; m++)
        zp[m] = pack2(zsh[tid*ZSTR + 2*m], zsh[tid*ZSTR + 2*m + 1]);
    __syncthreads();

    // ---------------- prologue pass B: z2 (cols 64..127) -> smem (passive) -----
    #pragma unroll 4
    for (int it = 0; it < 64; it++) {
        int idx = it * TPB + tid;
        int row = idx >> 6, col = idx & 63;
        size_t go = (size_t)row * ZSv + 64 + col;
        float ep = eps[r0*ZSv + go];
        float lv = logvar[bbase + go];
        float mn = mean[bbase + go];
        zsh[row*ZSTR + col] = fmaf(ep, __expf(0.5f*lv), mn);
        float c = fmaf(ep, ep, lv);
        #pragma unroll
        for (int o = 16; o; o >>= 1) c += __shfl_xor_sync(0xFFFFFFFFu, c, o);
        if (lane == 0) rowpart[row*4 + 2 + ((tid >> 5) & 1)] = c;
    }

    float lg = 0.f;        // sum of log2(1 + e^{-sr}) ; logdet = -ln2 * lg

    // ---------------- 4 flow half-steps --------------------------------------
    #pragma unroll 1
    for (int s = 0; s < 4; s++) {
        __syncthreads();
        {   // stage this half-step's weights (zero-padded)
            const float* W0g = W0 + s*(HSv*ZHv);
            #pragma unroll 1
            for (int i = tid; i < HSP*ZHv; i += TPB)
                w0sh[i] = (i < HSv*ZHv) ? W0g[i] : 0.f;
            const float* W1g = W1 + s*(ZHv*HSv);
            const float* W2g = W2 + s*(ZHv*HSv);
            #pragma unroll 1
            for (int i = tid; i < ZHv*HSP; i += TPB) {
                int l = i / HSP;
                int j = i - l*HSP;
                float v1 = 0.f, v2 = 0.f;
                if (j < HSv) { v1 = W1g[l*HSv + j]; v2 = W2g[l*HSv + j]; }
                w1sh[i] = v1;  w2sh[i] = v2;
            }
            if (tid < HSP) b0sh[tid] = (tid < HSv) ? b0[s*HSv + tid] : 0.f;
            if (tid < ZHv) { b1sh[tid] = b1[s*ZHv + tid]; b2sh[tid] = b2[s*ZHv + tid]; }
        }
        __syncthreads();

        // ---- h[j] = tanh(W0[j,:] . zsrc + b0[j]) ; zsrc from registers -------
        ull hp[26];
        #pragma unroll
        for (int c4 = 0; c4 < 13; c4++) {
            const float* wr = w0sh + (c4*4)*ZHv;
            ull a0 = pack2(b0sh[c4*4+0], 0.f);
            ull a1 = pack2(b0sh[c4*4+1], 0.f);
            ull a2 = pack2(b0sh[c4*4+2], 0.f);
            ull a3 = pack2(b0sh[c4*4+3], 0.f);
            #pragma unroll
            for (int kq = 0; kq < 16; kq++) {
                ulonglong2 q0 = *reinterpret_cast<const ulonglong2*>(wr + 0*ZHv + kq*4);
                ulonglong2 q1 = *reinterpret_cast<const ulonglong2*>(wr + 1*ZHv + kq*4);
                ulonglong2 q2 = *reinterpret_cast<const ulonglong2*>(wr + 2*ZHv + kq*4);
                ulonglong2 q3 = *reinterpret_cast<const ulonglong2*>(wr + 3*ZHv + kq*4);
                const ull zlo = zp[2*kq], zhi = zp[2*kq+1];
                a0 = ffma2(q0.x, zlo, a0);  a0 = ffma2(q0.y, zhi, a0);
                a1 = ffma2(q1.x, zlo, a1);  a1 = ffma2(q1.y, zhi, a1);
                a2 = ffma2(q2.x, zlo, a2);  a2 = ffma2(q2.y, zhi, a2);
                a3 = ffma2(q3.x, zlo, a3);  a3 = ffma2(q3.y, zhi, a3);
            }
            float2 p0 = unpack2(a0), p1 = unpack2(a1), p2 = unpack2(a2), p3 = unpack2(a3);
            float t0 = fast_tanh(p0.x + p0.y);
            float t1 = fast_tanh(p1.x + p1.y);
            float t2 = fast_tanh(p2.x + p2.y);
            float t3 = fast_tanh(p3.x + p3.y);
            hp[c4*2]   = pack2(t0, t1);
            hp[c4*2+1] = pack2(t2, t3);
        }

        // ---- mew/sig GEMVs ; update passive half (smem), swap into regs ------
        float* zr = zsh + tid*ZSTR;
        #pragma unroll
        for (int m = 0; m < 32; m++) {
            const int l0 = 2*m, l1 = 2*m + 1;
            const float* w1a = w1sh + l0*HSP;
            const float* w1b = w1sh + l1*HSP;
            const float* w2a = w2sh + l0*HSP;
            const float* w2b = w2sh + l1*HSP;
            ull ma0=0, ma1=0, mb0=0, mb1=0, sa0=0, sa1=0, sb0=0, sb1=0;
            #pragma unroll
            for (int p = 0; p < 13; p++) {
                const ull h0 = hp[2*p], h1 = hp[2*p+1];
                ulonglong2 q;
                q = *reinterpret_cast<const ulonglong2*>(w1a + p*4);
                ma0 = ffma2(q.x, h0, ma0);  ma1 = ffma2(q.y, h1, ma1);
                q = *reinterpret_cast<const ulonglong2*>(w1b + p*4);
                mb0 = ffma2(q.x, h0, mb0);  mb1 = ffma2(q.y, h1, mb1);
                q = *reinterpret_cast<const ulonglong2*>(w2a + p*4);
                sa0 = ffma2(q.x, h0, sa0);  sa1 = ffma2(q.y, h1, sa1);
                q = *reinterpret_cast<const ulonglong2*>(w2b + p*4);
                sb0 = ffma2(q.x, h0, sb0);  sb1 = ffma2(q.y, h1, sb1);
            }
            float2 u;
            u = unpack2(ma0); float mew0 = u.x + u.y;
            u = unpack2(ma1); mew0 += u.x + u.y;  mew0 += b1sh[l0];
            u = unpack2(mb0); float mew1 = u.x + u.y;
            u = unpack2(mb1); mew1 += u.x + u.y;  mew1 += b1sh[l1];
            u = unpack2(sa0); float sr0 = u.x + u.y;
            u = unpack2(sa1); sr0 += u.x + u.y;   sr0 += b2sh[l0];
            u = unpack2(sb0); float sr1 = u.x + u.y;
            u = unpack2(sb1); sr1 += u.x + u.y;   sr1 += b2sh[l1];

            float e0 = __expf(-sr0), e1 = __expf(-sr1);
            float g0 = __fdividef(1.f, 1.f + e0);
            float g1 = __fdividef(1.f, 1.f + e1);
            lg += __log2f(1.f + e0) + __log2f(1.f + e1);

            float2 oldz = unpack2(zp[m]);
            float t0 = zr[l0], t1 = zr[l1];
            float zn0 = fmaf(t0, g0, mew0);
            float zn1 = fmaf(t1, g1, mew1);
            zr[l0] = oldz.x;  zr[l1] = oldz.y;    // old src becomes passive half
            zp[m]  = pack2(zn0, zn1);             // updated tgt becomes new src
        }
    }

    // After s=3: zp = z1 (final), zsh = z2 (final)
    __syncthreads();
    #pragma unroll 4
    for (int it = 0; it < 64; it++) {          // write z2 half, coalesced
        int idx = it * TPB + tid;
        int row = idx >> 6, col = idx & 63;
        out[(r0 + row)*ZSv + 64 + col] = zsh[row*ZSTR + col];
    }
    __syncthreads();
    #pragma unroll
    for (int m = 0; m < 32; m++) {             // dump z1 regs -> smem
        float2 v = unpack2(zp[m]);
        zsh[tid*ZSTR + 2*m]     = v.x;
        zsh[tid*ZSTR + 2*m + 1] = v.y;
    }
    __syncthreads();
    #pragma unroll 4
    for (int it = 0; it < 64; it++) {          // write z1 half, coalesced
        int idx = it * TPB + tid;
        int row = idx >> 6, col = idx & 63;
        out[(r0 + row)*ZSv + col] = zsh[row*ZSTR + col];
    }

    float rs = rowpart[tid*4+0] + rowpart[tid*4+1] + rowpart[tid*4+2] + rowpart[tid*4+3];
    float logq = -0.5f * ((float)ZSv * 1.8378770664093453f + rs);   // ln(2*pi)
    // logpz = logq - logdet = logq + ln2 * lg
    out[(size_t)ROWS*ZSv + r0 + tid] = logq + 0.69314718055994531f * lg;
}

extern "C" void kernel_launch(void* const* d_in, const int* in_sizes, int n_in,
                              void* d_out, int out_size) {
    (void)in_sizes; (void)n_in; (void)out_size;
    const float* mean   = (const float*)d_in[0];
    const float* logvar = (const float*)d_in[1];
    const float* eps    = (const float*)d_in[2];
    const float* W0     = (const float*)d_in[3];
    const float* b0     = (const float*)d_in[4];
    const float* W1     = (const float*)d_in[5];
    const float* b1     = (const float*)d_in[6];
    const float* W2     = (const float*)d_in[7];
    const float* b2     = (const float*)d_in[8];
    float* out = (float*)d_out;

    cudaFuncSetAttribute(flow_kernel, cudaFuncAttributeMaxDynamicSharedMemorySize, SMEM_BYTES);
    flow_kernel<<<NBLK, TPB, SMEM_BYTES>>>(mean, logvar, eps, W0, b0, W1, b1, W2, b2, out);
}

// round 3
// speedup vs baseline: 1.0366x; 1.0366x over previous
#include <cuda_runtime.h>

// Flow1: K=32, B=4096, ZS=128, ZH=64, HS=50, NF=2
#define KK   32
#define BB   4096
#define ZSv  128
#define ZHv  64
#define HSv  50
#define HSP  52            // HS padded to multiple of 4 (zero-padded)
#define ROWS (KK*BB)       // 131072
#define TPB  128
#define RPC  256           // rows per CTA (2 rows per thread: t and t+128)
#define NBLK (ROWS/RPC)    // 512
#define ZSTR 132           // 4*33 (odd multiple of 4) -> conflict-free quad LDS

#define SMEM_FLOATS (RPC*ZSTR + HSP*ZHv + 2*ZHv*HSP + HSP + 2*ZHv + RPC*4)
#define SMEM_BYTES  (SMEM_FLOATS * 4)   // ~180 KB -> 1 CTA/SM

typedef unsigned long long ull;

__device__ __forceinline__ ull ffma2(ull a, ull b, ull c) {
    ull d;
    asm("fma.rn.f32x2 %0, %1, %2, %3;" : "=l"(d) : "l"(a), "l"(b), "l"(c));
    return d;
}
__device__ __forceinline__ ull pack2(float lo, float hi) {
    ull r;
    asm("mov.b64 %0, {%1, %2};" : "=l"(r) : "f"(lo), "f"(hi));
    return r;
}
__device__ __forceinline__ float2 unpack2(ull v) {
    float lo, hi;
    asm("mov.b64 {%0, %1}, %2;" : "=f"(lo), "=f"(hi) : "l"(v));
    return make_float2(lo, hi);
}
__device__ __forceinline__ float fast_tanh(float x) {
    float e = __expf(-2.f * fabsf(x));
    float t = __fdividef(1.f - e, 1.f + e);
    return copysignf(t, x);
}

__global__ void __launch_bounds__(TPB, 1) flow_kernel(
    const float* __restrict__ mean, const float* __restrict__ logvar,
    const float* __restrict__ eps,
    const float* __restrict__ W0, const float* __restrict__ b0,
    const float* __restrict__ W1, const float* __restrict__ b1,
    const float* __restrict__ W2, const float* __restrict__ b2,
    float* __restrict__ out)
{
    extern __shared__ float sm[];
    float* zsh     = sm;                    // [RPC][ZSTR] cols 0..63 z1, 64..127 z2
    float* w0sh    = zsh  + RPC*ZSTR;       // [HSP][ZHv]  rows j>=50 zero
    float* w1sh    = w0sh + HSP*ZHv;        // [ZHv][HSP]  cols j>=50 zero
    float* w2sh    = w1sh + ZHv*HSP;        // [ZHv][HSP]
    float* b0sh    = w2sh + ZHv*HSP;        // [HSP]
    float* b1sh    = b0sh + HSP;            // [ZHv]
    float* b2sh    = b1sh + ZHv;            // [ZHv]
    float* rowpart = b2sh + ZHv;            // [RPC][4]

    const int tid  = threadIdx.x;
    const int lane = tid & 31;
    const int warp = tid >> 5;
    const size_t r0    = (size_t)blockIdx.x * RPC;
    const size_t bbase = (size_t)(r0 & (BB-1)) * ZSv;

    // ---------------- prologue: z = eps*exp(0.5*lv)+mean; rowsum(lv+eps^2) -----
    #pragma unroll 4
    for (int row = 0; row < RPC; row++) {
        size_t go = (size_t)row * ZSv + tid;     // one full row per iteration
        float ep = eps[r0*ZSv + go];
        float lv = logvar[bbase + go];
        float mn = mean[bbase + go];
        zsh[row*ZSTR + tid] = fmaf(ep, __expf(0.5f*lv), mn);
        float c = fmaf(ep, ep, lv);
        #pragma unroll
        for (int o = 16; o; o >>= 1) c += __shfl_xor_sync(0xFFFFFFFFu, c, o);
        if (lane == 0) rowpart[row*4 + warp] = c;
    }

    float lgA = 0.f, lgB = 0.f;       // sum log2(1+e^{-sr}) per owned row

    float* zrA = zsh + tid*ZSTR;            // row A = t
    float* zrB = zsh + (tid+128)*ZSTR;      // row B = t+128

    // ---------------- 4 flow half-steps ---------------------------------------
    #pragma unroll 1
    for (int s = 0; s < 4; s++) {
        __syncthreads();
        {   // stage this half-step's weights (zero-padded)
            const float* W0g = W0 + s*(HSv*ZHv);
            #pragma unroll 1
            for (int i = tid; i < HSP*ZHv; i += TPB)
                w0sh[i] = (i < HSv*ZHv) ? W0g[i] : 0.f;
            const float* W1g = W1 + s*(ZHv*HSv);
            const float* W2g = W2 + s*(ZHv*HSv);
            #pragma unroll 1
            for (int i = tid; i < ZHv*HSP; i += TPB) {
                int l = i / HSP;
                int j = i - l*HSP;
                float v1 = 0.f, v2 = 0.f;
                if (j < HSv) { v1 = W1g[l*HSv + j]; v2 = W2g[l*HSv + j]; }
                w1sh[i] = v1;  w2sh[i] = v2;
            }
            if (tid < HSP) b0sh[tid] = (tid < HSv) ? b0[s*HSv + tid] : 0.f;
            if (tid < ZHv) { b1sh[tid] = b1[s*ZHv + tid]; b2sh[tid] = b2[s*ZHv + tid]; }
        }
        __syncthreads();

        const int srcoff = (s & 1) ? 64 : 0;
        const int tgtoff = 64 - srcoff;
        const float* zA = zrA + srcoff;
        const float* zB = zrB + srcoff;

        // ---- h = tanh(W0 . zsrc + b0) for both rows; weights loaded ONCE -----
        float hA[HSP], hB[HSP];
        #pragma unroll
        for (int c4 = 0; c4 < 4; c4++) {
            ull aA[13], aB[13];
            #pragma unroll
            for (int jj = 0; jj < 13; jj++) {
                float b = b0sh[c4*13 + jj];
                aA[jj] = pack2(b, 0.f);
                aB[jj] = pack2(b, 0.f);
            }
            #pragma unroll 4
            for (int kq = 0; kq < 16; kq++) {
                ulonglong2 zqA = *reinterpret_cast<const ulonglong2*>(zA + 4*kq);
                ulonglong2 zqB = *reinterpret_cast<const ulonglong2*>(zB + 4*kq);
                #pragma unroll
                for (int jj = 0; jj < 13; jj++) {
                    ulonglong2 wq = *reinterpret_cast<const ulonglong2*>(
                        w0sh + (c4*13 + jj)*ZHv + 4*kq);
                    aA[jj] = ffma2(wq.x, zqA.x, aA[jj]);
                    aA[jj] = ffma2(wq.y, zqA.y, aA[jj]);
                    aB[jj] = ffma2(wq.x, zqB.x, aB[jj]);
                    aB[jj] = ffma2(wq.y, zqB.y, aB[jj]);
                }
            }
            #pragma unroll
            for (int jj = 0; jj < 13; jj++) {
                float2 pA = unpack2(aA[jj]);
                float2 pB = unpack2(aB[jj]);
                hA[c4*13 + jj] = fast_tanh(pA.x + pA.y);
                hB[c4*13 + jj] = fast_tanh(pB.x + pB.y);
            }
        }
        ull hpA[26], hpB[26];
        #pragma unroll
        for (int p = 0; p < 26; p++) {
            hpA[p] = pack2(hA[2*p], hA[2*p+1]);
            hpB[p] = pack2(hB[2*p], hB[2*p+1]);
        }

        // ---- mew/sig GEMVs: 16 blocks of 4 outputs; weights loaded ONCE ------
        float* ztA = zrA + tgtoff;
        float* ztB = zrB + tgtoff;
        #pragma unroll 1
        for (int mb = 0; mb < 16; mb++) {
            const int l0 = mb*4;
            ull mA[4], mB[4], sA[4], sB[4];
            #pragma unroll
            for (int l = 0; l < 4; l++) { mA[l]=0; mB[l]=0; sA[l]=0; sB[l]=0; }
            const float* w1b = w1sh + l0*HSP;
            const float* w2b = w2sh + l0*HSP;
            #pragma unroll
            for (int p = 0; p < 13; p++) {
                const ull hA0 = hpA[2*p], hA1 = hpA[2*p+1];
                const ull hB0 = hpB[2*p], hB1 = hpB[2*p+1];
                #pragma unroll
                for (int l = 0; l < 4; l++) {
                    ulonglong2 w1q = *reinterpret_cast<const ulonglong2*>(w1b + l*HSP + 4*p);
                    ulonglong2 w2q = *reinterpret_cast<const ulonglong2*>(w2b + l*HSP + 4*p);
                    mA[l] = ffma2(w1q.x, hA0, mA[l]);
                    mA[l] = ffma2(w1q.y, hA1, mA[l]);
                    mB[l] = ffma2(w1q.x, hB0, mB[l]);
                    mB[l] = ffma2(w1q.y, hB1, mB[l]);
                    sA[l] = ffma2(w2q.x, hA0, sA[l]);
                    sA[l] = ffma2(w2q.y, hA1, sA[l]);
                    sB[l] = ffma2(w2q.x, hB0, sB[l]);
                    sB[l] = ffma2(w2q.y, hB1, sB[l]);
                }
            }
            // load target quads, update, store back
            float4 ztqA = *reinterpret_cast<const float4*>(ztA + l0);
            float4 ztqB = *reinterpret_cast<const float4*>(ztB + l0);
            float znA[4], znB[4];
            float ztav[4] = {ztqA.x, ztqA.y, ztqA.z, ztqA.w};
            float ztbv[4] = {ztqB.x, ztqB.y, ztqB.z, ztqB.w};
            #pragma unroll
            for (int l = 0; l < 4; l++) {
                float2 u;
                u = unpack2(mA[l]); float mewA = u.x + u.y + b1sh[l0+l];
                u = unpack2(mB[l]); float mewB = u.x + u.y + b1sh[l0+l];
                u = unpack2(sA[l]); float srA  = u.x + u.y + b2sh[l0+l];
                u = unpack2(sB[l]); float srB  = u.x + u.y + b2sh[l0+l];
                float eA = __expf(-srA), eB = __expf(-srB);
                float gA = __fdividef(1.f, 1.f + eA);
                float gB = __fdividef(1.f, 1.f + eB);
                lgA += __log2f(1.f + eA);
                lgB += __log2f(1.f + eB);
                znA[l] = fmaf(ztav[l], gA, mewA);
                znB[l] = fmaf(ztbv[l], gB, mewB);
            }
            *reinterpret_cast<float4*>(ztA + l0) = make_float4(znA[0],znA[1],znA[2],znA[3]);
            *reinterpret_cast<float4*>(ztB + l0) = make_float4(znB[0],znB[1],znB[2],znB[3]);
        }
    }

    // ---------------- epilogue ------------------------------------------------
    __syncthreads();
    #pragma unroll 4
    for (int row = 0; row < RPC; row++)
        out[(r0 + row)*ZSv + tid] = zsh[row*ZSTR + tid];

    float rsA = rowpart[tid*4+0] + rowpart[tid*4+1] + rowpart[tid*4+2] + rowpart[tid*4+3];
    float rsB = rowpart[(tid+128)*4+0] + rowpart[(tid+128)*4+1]
              + rowpart[(tid+128)*4+2] + rowpart[(tid+128)*4+3];
    const float C = -0.5f * (float)ZSv * 1.8378770664093453f;   // -64*ln(2*pi)
    // logpz = logq - logdet = logq + ln2 * lg
    out[(size_t)ROWS*ZSv + r0 + tid]       = (C - 0.5f*rsA) + 0.69314718055994531f * lgA;
    out[(size_t)ROWS*ZSv + r0 + 128 + tid] = (C - 0.5f*rsB) + 0.69314718055994531f * lgB;
}

extern "C" void kernel_launch(void* const* d_in, const int* in_sizes, int n_in,
                              void* d_out, int out_size) {
    (void)in_sizes; (void)n_in; (void)out_size;
    const float* mean   = (const float*)d_in[0];
    const float* logvar = (const float*)d_in[1];
    const float* eps    = (const float*)d_in[2];
    const float* W0     = (const float*)d_in[3];
    const float* b0     = (const float*)d_in[4];
    const float* W1     = (const float*)d_in[5];
    const float* b1     = (const float*)d_in[6];
    const float* W2     = (const float*)d_in[7];
    const float* b2     = (const float*)d_in[8];
    float* out = (float*)d_out;

    cudaFuncSetAttribute(flow_kernel, cudaFuncAttributeMaxDynamicSharedMemorySize, SMEM_BYTES);
    flow_kernel<<<NBLK, TPB, SMEM_BYTES>>>(mean, logvar, eps, W0, b0, W1, b1, W2, b2, out);
}